// round 10
// baseline (speedup 1.0000x reference)
#include <cuda_runtime.h>
#include <cuda_fp16.h>
#include <math.h>

// WaveNet collapsed to the last-sample 32-dim recurrence (k=0 tap only):
//   u_L = tanh(F_L x) * sigmoid(G_L x);  x = (R_L + I) u;  skip += S_L u
//   out = end2 @ relu(end1 @ relu(skip) + b1) + b2
//
// R10 (= R9 + compile fix): ONE kernel.
//   Phase 0: all 8 blocks pack 1/8 of the weights each (batched, exact
//            compile-time trip counts), then cross a global spin barrier.
//   Phase 1: warp 0 = serial recurrence from a double-buffered smem ring;
//            warps 1-7 = ring producers + fp16 skip GEMM one chunk behind;
//            then the fp16 end1/end2 head.

#define NL   40
#define RC   32
#define SC   256
#define CIN  6
#define T_IN 8192
#define FULLM 0xffffffffu

#define CH   4                 // layers per chunk
#define NCH  (NL / CH)         // 10 chunks
#define LW   768               // float4 per layer (3072 floats: F@0 G@256 R@512)
#define CW   (CH * LW)         // float4 per chunk = 3072
#define RING_BYTES (2 * CW * 16)   // 98304

typedef unsigned long long u64;

__device__ float  g_pk[NL * 3072];           // packed F'(-2F)/G'(-G)/R'(R+I), fp32
__device__ __half g_skipH[(NL * RC) * SC];   // [kg8][c][8kk] fp16, 655 KB
__device__ __half g_end1H[SC * SC];          // [jg8][c][8jj] fp16, 128 KB
__device__ float  g_xs0[8 * RC];
__device__ unsigned g_cnt;                   // zero-init
__device__ unsigned g_gen;                   // zero-init

__device__ __forceinline__ void fma2(u64& d, u64 a, u64 b) {
    asm("fma.rn.f32x2 %0, %1, %2, %3;" : "=l"(d) : "l"(a), "l"(b), "l"(d));
}
__device__ __forceinline__ void add2(u64& d, u64 a, u64 b) {
    asm("add.rn.f32x2 %0, %1, %2;" : "=l"(d) : "l"(a), "l"(b));
}
__device__ __forceinline__ float2 upk(u64 v) {
    float2 r; asm("mov.b64 {%0, %1}, %2;" : "=f"(r.x), "=f"(r.y) : "l"(v));
    return r;
}
__device__ __forceinline__ unsigned h2u(__half2 h) {
    unsigned u; *reinterpret_cast<__half2*>(&u) = h; return u;
}
__device__ __forceinline__ __half2 u2h(unsigned u) {
    return *reinterpret_cast<__half2*>(&u);
}
__device__ __forceinline__ uint4 pack8h(float4 a, float4 c) {
    uint4 o;
    o.x = h2u(__floats2half2_rn(a.x, a.y));
    o.y = h2u(__floats2half2_rn(a.z, a.w));
    o.z = h2u(__floats2half2_rn(c.x, c.y));
    o.w = h2u(__floats2half2_rn(c.z, c.w));
    return o;
}
__device__ __forceinline__ float dot8h(uint4 s8, const float* u) {
    const float2 p0 = __half22float2(u2h(s8.x));
    const float2 p1 = __half22float2(u2h(s8.y));
    const float2 p2 = __half22float2(u2h(s8.z));
    const float2 p3 = __half22float2(u2h(s8.w));
    float a = fmaf(p0.x, u[0], 0.f);
    a = fmaf(p0.y, u[1], a);
    a = fmaf(p1.x, u[2], a);
    a = fmaf(p1.y, u[3], a);
    a = fmaf(p2.x, u[4], a);
    a = fmaf(p2.y, u[5], a);
    a = fmaf(p3.x, u[6], a);
    a = fmaf(p3.y, u[7], a);
    return a;
}

extern __shared__ float ring[];    // RING_BYTES dynamic smem

__global__ __launch_bounds__(256, 1)
void wn_main(const float* __restrict__ x,
             const float* __restrict__ start_w,
             const float* __restrict__ filter_w,
             const float* __restrict__ gate_w,
             const float* __restrict__ res_w,
             const float* __restrict__ skip_w,
             const float* __restrict__ end1_w,
             const float* __restrict__ end1_b,
             const float* __restrict__ end2_w,
             const float* __restrict__ end2_b,
             float* __restrict__ out)
{
    const int b    = blockIdx.x;
    const int tid  = threadIdx.x;
    const int lane = tid & 31;
    const int warp = tid >> 5;
    const int gtid = b * 256 + tid;         // 0..2047

    __shared__ __align__(16) float us_all[NL * RC];   // 5.1 KB
    __shared__ __align__(16) float xs[RC];
    __shared__ __align__(16) float hs[SC];
    __shared__ float red8[8];

    // ================= phase 0: distributed pack (1/8 per block) ==========
    // g_pk: 30720 float4 items, 15/thread exact
    #pragma unroll
    for (int k = 0; k < 15; k++) {
        const int idx = gtid + 2048 * k;
        const int L  = idx / LW;
        const int r  = idx % LW;
        const int sec = r >> 8;              // 0=F' 1=G' 2=R'
        const int t  = r & 255;
        const int jg = t >> 5;
        const int i  = t & 31;
        float4 o;
        if (sec < 2) {
            const float* src = (sec ? gate_w : filter_w) + L * 2048 + i * 64 + 8 * jg;
            const float4 a = *(const float4*)src;
            const float4 c = *(const float4*)(src + 4);
            const float sc = sec ? -1.f : -2.f;
            o.x = sc * a.x; o.y = sc * a.z; o.z = sc * c.x; o.w = sc * c.z;
        } else {
            o = *(const float4*)(res_w + L * 1024 + i * 32 + 4 * jg);
            if ((i >> 2) == jg) (&o.x)[i & 3] += 1.f;   // bake identity
        }
        ((float4*)g_pk)[idx] = o;
    }
    // g_skipH: 40960 uint4 items (8 halves each), 20/thread exact
    #pragma unroll
    for (int k = 0; k < 20; k++) {
        const int i8  = gtid + 2048 * k;
        const int kg8 = i8 >> 8;
        const int c   = i8 & 255;
        const int k0  = kg8 * 8;
        const int L   = k0 >> 5;
        const int j0  = k0 & 31;
        const float* src = skip_w + L * (SC * RC) + c * RC + j0;
        ((uint4*)g_skipH)[i8] = pack8h(*(const float4*)src, *(const float4*)(src + 4));
    }
    // g_end1H: 8192 uint4 items, 4/thread exact
    #pragma unroll
    for (int k = 0; k < 4; k++) {
        const int i8  = gtid + 2048 * k;
        const int jg8 = i8 >> 8;
        const int c   = i8 & 255;
        const float* src = end1_w + c * SC + jg8 * 8;
        ((uint4*)g_end1H)[i8] = pack8h(*(const float4*)src, *(const float4*)(src + 4));
    }
    // g_xs0: start conv
    if (gtid < 8 * RC) {
        const int bb = gtid / RC, i = gtid % RC;
        float s = 0.f;
        #pragma unroll
        for (int ci = 0; ci < CIN; ci++)
            s += start_w[i * CIN + ci] * x[(bb * CIN + ci) * T_IN + (T_IN - 1)];
        g_xs0[gtid] = s;
    }

    // ---- global spin barrier (sense via generation counter; 8 co-resident
    // blocks; generation persists across graph replays) ----
    __threadfence();
    __syncthreads();
    if (tid == 0) {
        const unsigned gen = *(volatile unsigned*)&g_gen;
        const unsigned old = atomicAdd(&g_cnt, 1u);
        if (old == 7u) {
            atomicExch(&g_cnt, 0u);
            __threadfence();
            atomicAdd(&g_gen, 1u);
        } else {
            while (*(volatile unsigned*)&g_gen == gen) { }
        }
    }
    __syncthreads();
    __threadfence();

    // ================= phase 1: recurrence + pipelined skip ================
    // skip-thread channel mapping: warps 1-7 -> c0 in [0,224);
    // warp 1 additionally owns c1 in [224,256).
    const int  c0   = tid - 32;
    const bool dual = (warp == 1);
    const int  c1   = tid + 192;
    float acc0 = 0.f, acc1 = 0.f;

    // prologue: batched copy of chunk 0 (12 float4 each, exact)
    {
        const float4* src = (const float4*)g_pk;
        float4*       dst = (float4*)ring;
        float4 t[12];
        #pragma unroll
        for (int k = 0; k < 12; k++) t[k] = src[tid + 256 * k];
        #pragma unroll
        for (int k = 0; k < 12; k++) dst[tid + 256 * k] = t[k];
    }
    if (warp == 0) xs[lane] = g_xs0[b * RC + lane];
    __syncthreads();

    for (int q = 0; q <= NCH; q++) {
        if (warp == 0) {
            if (q < NCH) {
                const float4* wc = (const float4*)ring + (q & 1) * CW;
                #pragma unroll
                for (int l = 0; l < CH; l++) {
                    const int L = q * CH + l;
                    const float4* wl = wc + l * LW + lane;

                    // phase A: f'/g' GEMV (F'=-2F, G'=-G baked in)
                    u64 fa = 0ull, fb = 0ull, ga = 0ull, gb = 0ull;
                    #pragma unroll
                    for (int jg = 0; jg < 8; jg++) {
                        const ulonglong2 xv = *(const ulonglong2*)&xs[4 * jg];
                        const ulonglong2 Fw = *(const ulonglong2*)(wl + jg * 32);
                        const ulonglong2 Gw = *(const ulonglong2*)(wl + 256 + jg * 32);
                        fma2(fa, Fw.x, xv.x); fma2(fb, Fw.y, xv.y);
                        fma2(ga, Gw.x, xv.x); fma2(gb, Gw.y, xv.y);
                    }
                    add2(fa, fa, fb);
                    add2(ga, ga, gb);
                    const float2 fp = upk(fa);
                    const float2 gp = upk(ga);
                    const float e1 = __expf(fp.x + fp.y);   // e^{-2f}
                    const float e2 = __expf(gp.x + gp.y);   // e^{-g}
                    // u = tanh(f)*sig(g) = (1-e1)/((1+e1)(1+e2))
                    const float u = __fdividef(1.f - e1, (1.f + e1) * (1.f + e2));
                    us_all[L * RC + lane] = u;
                    __syncwarp();

                    // phase B: x = (R+I) u
                    u64 ra = 0ull, rb = 0ull;
                    #pragma unroll
                    for (int jg = 0; jg < 8; jg++) {
                        const ulonglong2 uv = *(const ulonglong2*)&us_all[L * RC + 4 * jg];
                        const ulonglong2 Rw = *(const ulonglong2*)(wl + 512 + jg * 32);
                        fma2(ra, Rw.x, uv.x); fma2(rb, Rw.y, uv.y);
                    }
                    add2(ra, ra, rb);
                    const float2 rp = upk(ra);
                    xs[lane] = rp.x + rp.y;
                    __syncwarp();
                }
            }
        } else {
            // producers: batched stage of chunk q+1 into the other ring slot
            if (q + 1 < NCH) {
                const float4* src = (const float4*)g_pk + (q + 1) * CW;
                float4*       dst = (float4*)ring + ((q + 1) & 1) * CW;
                const int t0 = tid - 32;           // 0..223
                float4 t[14];
                #pragma unroll
                for (int k = 0; k < 14; k++) {
                    const int i = t0 + 224 * k;
                    if (i < CW) t[k] = src[i];
                }
                #pragma unroll
                for (int k = 0; k < 14; k++) {
                    const int i = t0 + 224 * k;
                    if (i < CW) dst[i] = t[k];
                }
            }
            // fp16 skip GEMM for chunk q-1: 16 k-groups of 8
            if (q >= 1) {
                const int cq = q - 1;
                const uint4* sp = (const uint4*)g_skipH + (16 * cq) * 256;
                const float* up = us_all + cq * (CH * RC);
                #pragma unroll
                for (int kg8 = 0; kg8 < 16; kg8++) {
                    acc0 += dot8h(sp[kg8 * 256 + c0], up + 8 * kg8);
                    if (dual)
                        acc1 += dot8h(sp[kg8 * 256 + c1], up + 8 * kg8);
                }
            }
        }
        __syncthreads();
    }

    // ---- head (fp16 end1)
    if (warp > 0) {
        hs[c0] = fmaxf(acc0, 0.f);
        if (dual) hs[c1] = fmaxf(acc1, 0.f);
    }
    __syncthreads();

    float o = 0.f;
    if (warp > 0) {
        float e0 = end1_b[c0];
        float e1v = dual ? end1_b[c1] : 0.f;
        const uint4* ep = (const uint4*)g_end1H;
        #pragma unroll
        for (int jg8 = 0; jg8 < 32; jg8++) {
            e0 += dot8h(ep[jg8 * 256 + c0], hs + 8 * jg8);
            if (dual)
                e1v += dot8h(ep[jg8 * 256 + c1], hs + 8 * jg8);
        }
        o = end2_w[c0] * fmaxf(e0, 0.f);
        if (dual) o += end2_w[c1] * fmaxf(e1v, 0.f);
    }
    #pragma unroll
    for (int off = 16; off > 0; off >>= 1)
        o += __shfl_xor_sync(FULLM, o, off);
    if (lane == 0) red8[warp] = o;
    __syncthreads();
    if (tid == 0) {
        float tot = 0.f;
        #pragma unroll
        for (int w = 0; w < 8; w++) tot += red8[w];
        out[b] = tot + end2_b[0];
    }
}

extern "C" void kernel_launch(void* const* d_in, const int* in_sizes, int n_in,
                              void* d_out, int out_size)
{
    const float* x        = (const float*)d_in[0];
    const float* start_w  = (const float*)d_in[1];
    const float* filter_w = (const float*)d_in[2];
    const float* gate_w   = (const float*)d_in[3];
    const float* res_w    = (const float*)d_in[4];
    const float* skip_w   = (const float*)d_in[5];
    const float* end1_w   = (const float*)d_in[6];
    const float* end1_b   = (const float*)d_in[7];
    const float* end2_w   = (const float*)d_in[8];
    const float* end2_b   = (const float*)d_in[9];
    float* out = (float*)d_out;

    cudaFuncSetAttribute(wn_main,
                         cudaFuncAttributeMaxDynamicSharedMemorySize,
                         RING_BYTES);

    wn_main<<<8, 256, RING_BYTES>>>(x, start_w, filter_w, gate_w, res_w,
                                    skip_w, end1_w, end1_b, end2_w, end2_b,
                                    out);
}

// round 11
// speedup vs baseline: 1.3949x; 1.3949x over previous
#include <cuda_runtime.h>
#include <cuda_fp16.h>
#include <math.h>

// WaveNet collapsed to the last-sample 32-dim recurrence (k=0 tap only):
//   u_L = tanh(F_L x) * sigmoid(G_L x);  x = (R_L + I) u;  skip += S_L u
//   out = end2 @ relu(end1 @ relu(skip) + b1) + b2
//
// R11 = R7 two-kernel structure + fp16 skip/end1 (validated in R10).
//  1) wn_pack : vectorized repack. F'=-2F, G'=-G, R'=R+I (fp32);
//               skipT/end1T transposed AND converted to fp16.
//  2) wn_main : grid=8 (batch), 256 thr, 96KB smem weight ring.
//     warp 0    : recurrence from SMEM (LDS.128 + f32x2 FMAs).
//     warps 1-7 : batched ring producers + fp16 skip GEMM one chunk behind;
//                 then the fp16 end1/end2 head.

#define NL   40
#define RC   32
#define SC   256
#define CIN  6
#define T_IN 8192
#define FULLM 0xffffffffu

#define CH   4                 // layers per chunk
#define NCH  (NL / CH)         // 10 chunks
#define LW   768               // float4 per layer (3072 floats: F@0 G@256 R@512)
#define CW   (CH * LW)         // float4 per chunk = 3072
#define RING_BYTES (2 * CW * 16)   // 98304

typedef unsigned long long u64;

__device__ float  g_pk[NL * 3072];           // packed F'/G'/R', fp32, 491 KB
__device__ __half g_skipH[(NL * RC) * SC];   // [kg8][c][8kk] fp16, 655 KB
__device__ __half g_end1H[SC * SC];          // [jg8][c][8jj] fp16, 128 KB
__device__ float  g_xs0[8 * RC];

__device__ __forceinline__ void fma2(u64& d, u64 a, u64 b) {
    asm("fma.rn.f32x2 %0, %1, %2, %3;" : "=l"(d) : "l"(a), "l"(b), "l"(d));
}
__device__ __forceinline__ void add2(u64& d, u64 a, u64 b) {
    asm("add.rn.f32x2 %0, %1, %2;" : "=l"(d) : "l"(a), "l"(b));
}
__device__ __forceinline__ float2 upk(u64 v) {
    float2 r; asm("mov.b64 {%0, %1}, %2;" : "=f"(r.x), "=f"(r.y) : "l"(v));
    return r;
}
__device__ __forceinline__ unsigned h2u(__half2 h) {
    unsigned u; *reinterpret_cast<__half2*>(&u) = h; return u;
}
__device__ __forceinline__ __half2 u2h(unsigned u) {
    return *reinterpret_cast<__half2*>(&u);
}
__device__ __forceinline__ uint4 pack8h(float4 a, float4 c) {
    uint4 o;
    o.x = h2u(__floats2half2_rn(a.x, a.y));
    o.y = h2u(__floats2half2_rn(a.z, a.w));
    o.z = h2u(__floats2half2_rn(c.x, c.y));
    o.w = h2u(__floats2half2_rn(c.z, c.w));
    return o;
}
__device__ __forceinline__ float dot8h(uint4 s8, const float* u) {
    const float2 p0 = __half22float2(u2h(s8.x));
    const float2 p1 = __half22float2(u2h(s8.y));
    const float2 p2 = __half22float2(u2h(s8.z));
    const float2 p3 = __half22float2(u2h(s8.w));
    float a = fmaf(p0.x, u[0], 0.f);
    a = fmaf(p0.y, u[1], a);
    a = fmaf(p1.x, u[2], a);
    a = fmaf(p1.y, u[3], a);
    a = fmaf(p2.x, u[4], a);
    a = fmaf(p2.y, u[5], a);
    a = fmaf(p3.x, u[6], a);
    a = fmaf(p3.y, u[7], a);
    return a;
}

// ---------------------------------------------------------------- pack
// items: [0,NA) g_pk float4; [NA,NA+NB) g_skipH uint4(8 halves);
//        [..,+NC) g_end1H uint4; then 256 scalars for g_xs0.
__global__ void wn_pack(const float* __restrict__ x,
                        const float* __restrict__ start_w,
                        const float* __restrict__ filter_w,
                        const float* __restrict__ gate_w,
                        const float* __restrict__ res_w,
                        const float* __restrict__ skip_w,
                        const float* __restrict__ end1_w)
{
    const int NA = NL * LW;            // 30720
    const int NB = NL * RC * SC / 8;   // 40960
    const int NC = SC * SC / 8;        // 8192
    const int total = NA + NB + NC + 8 * RC;   // 80128

    for (int idx = blockIdx.x * blockDim.x + threadIdx.x; idx < total;
         idx += gridDim.x * blockDim.x) {
        if (idx < NA) {
            int L  = idx / LW;
            int r  = idx % LW;
            int sec = r >> 8;              // 0=F' 1=G' 2=R'
            int t  = r & 255;
            int jg = t >> 5;
            int i  = t & 31;
            float4 o;
            if (sec < 2) {
                const float* src = (sec ? gate_w : filter_w)
                                   + L * 2048 + i * 64 + 8 * jg;
                const float4 a = *(const float4*)src;
                const float4 c = *(const float4*)(src + 4);
                const float sc = sec ? -1.f : -2.f;
                o.x = sc * a.x; o.y = sc * a.z; o.z = sc * c.x; o.w = sc * c.z;
            } else {
                o = *(const float4*)(res_w + L * 1024 + i * 32 + 4 * jg);
                if ((i >> 2) == jg) (&o.x)[i & 3] += 1.f;   // bake identity
            }
            ((float4*)g_pk)[idx] = o;
        } else if (idx < NA + NB) {
            int i8  = idx - NA;
            int kg8 = i8 >> 8;
            int c   = i8 & 255;
            int k0  = kg8 * 8;
            int L   = k0 >> 5;
            int j0  = k0 & 31;
            const float* src = skip_w + L * (SC * RC) + c * RC + j0;
            ((uint4*)g_skipH)[i8] =
                pack8h(*(const float4*)src, *(const float4*)(src + 4));
        } else if (idx < NA + NB + NC) {
            int i8  = idx - NA - NB;
            int jg8 = i8 >> 8;
            int c   = i8 & 255;
            const float* src = end1_w + c * SC + jg8 * 8;
            ((uint4*)g_end1H)[i8] =
                pack8h(*(const float4*)src, *(const float4*)(src + 4));
        } else {
            int t = idx - NA - NB - NC;
            int b = t / RC, i = t % RC;
            float s = 0.f;
            #pragma unroll
            for (int ci = 0; ci < CIN; ci++)
                s += start_w[i * CIN + ci] * x[(b * CIN + ci) * T_IN + (T_IN - 1)];
            g_xs0[b * RC + i] = s;
        }
    }
}

// ---------------------------------------------------------------- main
extern __shared__ float ring[];    // RING_BYTES dynamic smem

__global__ __launch_bounds__(256, 1)
void wn_main(const float* __restrict__ end1_b,
             const float* __restrict__ end2_w,
             const float* __restrict__ end2_b,
             float* __restrict__ out)
{
    const int b    = blockIdx.x;
    const int tid  = threadIdx.x;
    const int lane = tid & 31;
    const int warp = tid >> 5;

    __shared__ __align__(16) float us_all[NL * RC];   // 5.1 KB
    __shared__ __align__(16) float xs[RC];
    __shared__ __align__(16) float hs[SC];
    __shared__ float red8[8];

    // skip-thread channel mapping: warps 1-7 -> c0 in [0,224);
    // warp 1 additionally owns c1 in [224,256).
    const int  c0   = tid - 32;
    const bool dual = (warp == 1);
    const int  c1   = tid + 192;
    float acc0 = 0.f, acc1 = 0.f;

    // prologue: batched copy of chunk 0 (12 float4 each, exact)
    {
        const float4* src = (const float4*)g_pk;
        float4*       dst = (float4*)ring;
        float4 t[12];
        #pragma unroll
        for (int k = 0; k < 12; k++) t[k] = src[tid + 256 * k];
        #pragma unroll
        for (int k = 0; k < 12; k++) dst[tid + 256 * k] = t[k];
    }
    if (warp == 0) xs[lane] = g_xs0[b * RC + lane];
    __syncthreads();

    for (int q = 0; q <= NCH; q++) {
        if (warp == 0) {
            if (q < NCH) {
                const float4* wc = (const float4*)ring + (q & 1) * CW;
                #pragma unroll
                for (int l = 0; l < CH; l++) {
                    const int L = q * CH + l;
                    const float4* wl = wc + l * LW + lane;

                    // phase A: f'/g' GEMV (F'=-2F, G'=-G baked in)
                    u64 fa = 0ull, fb = 0ull, ga = 0ull, gb = 0ull;
                    #pragma unroll
                    for (int jg = 0; jg < 8; jg++) {
                        const ulonglong2 xv = *(const ulonglong2*)&xs[4 * jg];
                        const ulonglong2 Fw = *(const ulonglong2*)(wl + jg * 32);
                        const ulonglong2 Gw = *(const ulonglong2*)(wl + 256 + jg * 32);
                        fma2(fa, Fw.x, xv.x); fma2(fb, Fw.y, xv.y);
                        fma2(ga, Gw.x, xv.x); fma2(gb, Gw.y, xv.y);
                    }
                    add2(fa, fa, fb);
                    add2(ga, ga, gb);
                    const float2 fp = upk(fa);
                    const float2 gp = upk(ga);
                    const float e1 = __expf(fp.x + fp.y);   // e^{-2f}
                    const float e2 = __expf(gp.x + gp.y);   // e^{-g}
                    // u = tanh(f)*sig(g) = (1-e1)/((1+e1)(1+e2))
                    const float u = __fdividef(1.f - e1, (1.f + e1) * (1.f + e2));
                    us_all[L * RC + lane] = u;
                    __syncwarp();

                    // phase B: x = (R+I) u
                    u64 ra = 0ull, rb = 0ull;
                    #pragma unroll
                    for (int jg = 0; jg < 8; jg++) {
                        const ulonglong2 uv = *(const ulonglong2*)&us_all[L * RC + 4 * jg];
                        const ulonglong2 Rw = *(const ulonglong2*)(wl + 512 + jg * 32);
                        fma2(ra, Rw.x, uv.x); fma2(rb, Rw.y, uv.y);
                    }
                    add2(ra, ra, rb);
                    const float2 rp = upk(ra);
                    xs[lane] = rp.x + rp.y;
                    __syncwarp();
                }
            }
        } else {
            // producers: batched stage of chunk q+1 into the other ring slot
            if (q + 1 < NCH) {
                const float4* src = (const float4*)g_pk + (q + 1) * CW;
                float4*       dst = (float4*)ring + ((q + 1) & 1) * CW;
                const int t0 = tid - 32;           // 0..223
                float4 t[14];
                #pragma unroll
                for (int k = 0; k < 14; k++) {
                    const int i = t0 + 224 * k;
                    if (i < CW) t[k] = src[i];
                }
                #pragma unroll
                for (int k = 0; k < 14; k++) {
                    const int i = t0 + 224 * k;
                    if (i < CW) dst[i] = t[k];
                }
            }
            // fp16 skip GEMM for chunk q-1: 16 k-groups of 8
            if (q >= 1) {
                const int cq = q - 1;
                const uint4* sp = (const uint4*)g_skipH + (16 * cq) * 256;
                const float* up = us_all + cq * (CH * RC);
                #pragma unroll
                for (int kg8 = 0; kg8 < 16; kg8++) {
                    acc0 += dot8h(sp[kg8 * 256 + c0], up + 8 * kg8);
                    if (dual)
                        acc1 += dot8h(sp[kg8 * 256 + c1], up + 8 * kg8);
                }
            }
        }
        __syncthreads();
    }

    // ---- head (fp16 end1)
    if (warp > 0) {
        hs[c0] = fmaxf(acc0, 0.f);
        if (dual) hs[c1] = fmaxf(acc1, 0.f);
    }
    __syncthreads();

    float o = 0.f;
    if (warp > 0) {
        float e0 = end1_b[c0];
        float e1v = dual ? end1_b[c1] : 0.f;
        const uint4* ep = (const uint4*)g_end1H;
        #pragma unroll
        for (int jg8 = 0; jg8 < 32; jg8++) {
            e0 += dot8h(ep[jg8 * 256 + c0], hs + 8 * jg8);
            if (dual)
                e1v += dot8h(ep[jg8 * 256 + c1], hs + 8 * jg8);
        }
        o = end2_w[c0] * fmaxf(e0, 0.f);
        if (dual) o += end2_w[c1] * fmaxf(e1v, 0.f);
    }
    #pragma unroll
    for (int off = 16; off > 0; off >>= 1)
        o += __shfl_xor_sync(FULLM, o, off);
    if (lane == 0) red8[warp] = o;
    __syncthreads();
    if (tid == 0) {
        float tot = 0.f;
        #pragma unroll
        for (int w = 0; w < 8; w++) tot += red8[w];
        out[b] = tot + end2_b[0];
    }
}

extern "C" void kernel_launch(void* const* d_in, const int* in_sizes, int n_in,
                              void* d_out, int out_size)
{
    const float* x        = (const float*)d_in[0];
    const float* start_w  = (const float*)d_in[1];
    const float* filter_w = (const float*)d_in[2];
    const float* gate_w   = (const float*)d_in[3];
    const float* res_w    = (const float*)d_in[4];
    const float* skip_w   = (const float*)d_in[5];
    const float* end1_w   = (const float*)d_in[6];
    const float* end1_b   = (const float*)d_in[7];
    const float* end2_w   = (const float*)d_in[8];
    const float* end2_b   = (const float*)d_in[9];
    float* out = (float*)d_out;

    cudaFuncSetAttribute(wn_main,
                         cudaFuncAttributeMaxDynamicSharedMemorySize,
                         RING_BYTES);

    wn_pack<<<157, 512>>>(x, start_w, filter_w, gate_w, res_w, skip_w, end1_w);
    wn_main<<<8, 256, RING_BYTES>>>(end1_b, end2_w, end2_b, out);
}